// round 2
// baseline (speedup 1.0000x reference)
#include <cuda_runtime.h>
#include <cuda_fp16.h>
#include <cstdint>

// ============================================================
// Problem constants
// ============================================================
#define BN   4
#define CN   16
#define HN   512
#define WN   512
#define HID  128
#define TILE 128      // pixels per CTA (one quarter of a row)

#define HALO_PITCH 132

// SMEM byte offsets (all 16B aligned)
#define SM_HALO  0                       // 16ch * 3 rows * 132 * f32 = 25344
#define SM_A     25344                   // A features: 128 rows * 144 B (f16 x 64, pitch-padded)
#define PITCH_A  144
#define SM_W0    43776                   // w0: 128 rows * 144 B
#define PITCH_W0 144
#define SM_W1    62208                   // w1: 16 rows * 272 B (f16 x 128, pitch-padded)
#define PITCH_W1 272
#define SM_UPD   66560                   // update stage: 128 * 17 * f32 = 8704
#define UPD_PITCH 17
#define SM_TOTAL 75264

// ============================================================
// PTX helpers (base sm_103-compatible: ldmatrix + mma.sync only)
// ============================================================
__device__ __forceinline__ uint32_t smem_u32(const void* p) {
    uint32_t a;
    asm("{ .reg .u64 t; cvta.to.shared.u64 t, %1; cvt.u32.u64 %0, t; }"
        : "=r"(a) : "l"(p));
    return a;
}

__device__ __forceinline__ void ldsm_x4(uint32_t* r, uint32_t addr) {
    asm volatile("ldmatrix.sync.aligned.m8n8.x4.shared.b16 {%0,%1,%2,%3}, [%4];"
                 : "=r"(r[0]), "=r"(r[1]), "=r"(r[2]), "=r"(r[3]) : "r"(addr));
}
__device__ __forceinline__ void ldsm_x2(uint32_t* r, uint32_t addr) {
    asm volatile("ldmatrix.sync.aligned.m8n8.x2.shared.b16 {%0,%1}, [%2];"
                 : "=r"(r[0]), "=r"(r[1]) : "r"(addr));
}

// D += A * B  (m16n8k16, f16 in, f32 accum)
__device__ __forceinline__ void mma16816(float* c, const uint32_t* a, const uint32_t* b) {
    asm volatile("mma.sync.aligned.m16n8k16.row.col.f32.f16.f16.f32 "
                 "{%0,%1,%2,%3}, {%4,%5,%6,%7}, {%8,%9}, {%0,%1,%2,%3};"
                 : "+f"(c[0]), "+f"(c[1]), "+f"(c[2]), "+f"(c[3])
                 : "r"(a[0]), "r"(a[1]), "r"(a[2]), "r"(a[3]),
                   "r"(b[0]), "r"(b[1]));
}

__device__ __forceinline__ uint32_t pack2(float a, float b) {
    __half2 h = __floats2half2_rn(a, b);
    return *reinterpret_cast<uint32_t*>(&h);
}

// ============================================================
// Kernel: one CTA = 128 consecutive pixels of one image row.
// 4 warps; warp w owns pixels [32w, 32w+32).
// Layer1: D1[32x128] = A[32x64] * W0^T  (bias folded in at k=48)
// Layer2: D2[32x16]  = relu(D1)[32x128] * W1^T  — fused in registers:
//   the m16n8 C-fragment of layer1 IS the m16n8k16 A-fragment of layer2
//   (two adjacent n8 tiles give the two k8 halves).
// ============================================================
__global__ void __launch_bounds__(128, 1) ca_mlp_kernel(
    const float* __restrict__ x,
    const float* __restrict__ w0,
    const float* __restrict__ b0,
    const float* __restrict__ w1,
    const float* __restrict__ ru,
    float* __restrict__ out)
{
    extern __shared__ char smem[];
    const uint32_t sbase = smem_u32(smem);
    float* s_halo = reinterpret_cast<float*>(smem + SM_HALO);
    float* s_upd  = reinterpret_cast<float*>(smem + SM_UPD);

    const int tid  = threadIdx.x;
    const int warp = tid >> 5;
    const int lane = tid & 31;
    const int g    = lane >> 2;   // group id (row within 8)
    const int t    = lane & 3;    // thread-in-group (col pair)

    const int bx   = blockIdx.x;
    const int wt   = bx & 3;
    const int hh   = (bx >> 2) & (HN - 1);
    const int bb   = bx >> 11;
    const int wpix = wt * TILE;

    // ---------------- Load weights to SMEM ----------------
    // w0: [128][64] f16, k<48 = w0, k==48 = b0 (bias-as-K), k>48 = 0
    for (int idx = tid; idx < 128 * 32; idx += 128) {
        const int o = idx >> 5;
        const int kp = (idx & 31) * 2;
        float v0 = 0.0f, v1 = 0.0f;
        if (kp < 48)      { v0 = w0[o * 48 + kp]; v1 = (kp + 1 < 48) ? w0[o * 48 + kp + 1] : 0.0f; }
        else if (kp == 48) v0 = b0[o];
        *reinterpret_cast<uint32_t*>(smem + SM_W0 + o * PITCH_W0 + kp * 2) = pack2(v0, v1);
    }
    // w1: [16][128] f16
    for (int idx = tid; idx < 16 * 64; idx += 128) {
        const int o = idx >> 6;
        const int kp = (idx & 63) * 2;
        *reinterpret_cast<uint32_t*>(smem + SM_W1 + o * PITCH_W1 + kp * 2) =
            pack2(w1[o * 128 + kp], w1[o * 128 + kp + 1]);
    }
    // x halo: 16 ch x 3 rows x 130 cols, zero-padded borders
    for (int idx = tid; idx < CN * 3 * 130; idx += 128) {
        const int c = idx / 390;
        const int rem = idx - c * 390;
        const int r = rem / 130;
        const int j = rem - r * 130;
        const int gh = hh + r - 1;
        const int gw = wpix + j - 1;
        float v = 0.0f;
        if ((unsigned)gh < (unsigned)HN && (unsigned)gw < (unsigned)WN)
            v = x[(((size_t)bb * CN + c) * HN + gh) * WN + gw];
        s_halo[(c * 3 + r) * HALO_PITCH + j] = v;
    }
    __syncthreads();

    // ---------------- Sobel features -> SMEM A (pixel tid = row tid) ----------------
    {
        float xv[CN], gx[CN], gy[CN];
        #pragma unroll
        for (int c = 0; c < CN; c++) {
            const float* hb = &s_halo[(c * 3) * HALO_PITCH + tid];
            const float p00 = hb[0], p01 = hb[1], p02 = hb[2];
            const float p10 = hb[HALO_PITCH],     p11 = hb[HALO_PITCH + 1],     p12 = hb[HALO_PITCH + 2];
            const float p20 = hb[2 * HALO_PITCH], p21 = hb[2 * HALO_PITCH + 1], p22 = hb[2 * HALO_PITCH + 2];
            xv[c] = p11;
            gx[c] = (p02 - p00) + 2.0f * (p12 - p10) + (p22 - p20);
            gy[c] = (p20 + 2.0f * p21 + p22) - (p00 + 2.0f * p01 + p02);
        }
        uint32_t* arow = reinterpret_cast<uint32_t*>(smem + SM_A + tid * PITCH_A);
        #pragma unroll
        for (int i = 0; i < 8; i++) {
            arow[i]      = pack2(xv[2 * i], xv[2 * i + 1]);
            arow[8 + i]  = pack2(gx[2 * i], gx[2 * i + 1]);
            arow[16 + i] = pack2(gy[2 * i], gy[2 * i + 1]);
        }
        arow[24] = pack2(1.0f, 0.0f);   // k=48 multiplies the b0 column
        #pragma unroll
        for (int i = 25; i < 32; i++) arow[i] = 0u;
    }
    __syncthreads();

    // ---------------- Preload A fragments (features, all 4 k-tiles) ----------------
    // a-frag addresses: lane L -> row m0+(L&15), col k0 + ((L>>4)*8) halves
    uint32_t afr[4][2][4];
    {
        const int m0 = warp * 32;
        #pragma unroll
        for (int kt = 0; kt < 4; kt++)
            #pragma unroll
            for (int mt = 0; mt < 2; mt++) {
                const int row = m0 + mt * 16 + (lane & 15);
                const int col = kt * 16 + ((lane >> 4) << 3);
                ldsm_x4(afr[kt][mt], sbase + SM_A + row * PITCH_A + col * 2);
            }
    }

    // ---------------- Preload W1 fragments (all 8 k2-tiles x 2 n2-tiles) ----------------
    uint32_t w1fr[8][2][2];
    #pragma unroll
    for (int k2 = 0; k2 < 8; k2++)
        #pragma unroll
        for (int n2 = 0; n2 < 2; n2++) {
            const int row = n2 * 8 + (lane & 7);
            const int col = k2 * 16 + (lane & 8);
            ldsm_x2(w1fr[k2][n2], sbase + SM_W1 + row * PITCH_W1 + col * 2);
        }

    // ---------------- Fused MLP ----------------
    float c2[2][2][4];
    #pragma unroll
    for (int mt = 0; mt < 2; mt++)
        #pragma unroll
        for (int n2 = 0; n2 < 2; n2++)
            #pragma unroll
            for (int j = 0; j < 4; j++) c2[mt][n2][j] = 0.0f;

    #pragma unroll
    for (int hc = 0; hc < 4; hc++) {        // hidden chunk of 32 units
        float c1[4][2][4];
        #pragma unroll
        for (int nt = 0; nt < 4; nt++)
            #pragma unroll
            for (int mt = 0; mt < 2; mt++)
                #pragma unroll
                for (int j = 0; j < 4; j++) c1[nt][mt][j] = 0.0f;

        #pragma unroll
        for (int kt = 0; kt < 4; kt++) {
            #pragma unroll
            for (int nt = 0; nt < 4; nt++) {
                uint32_t bfr[2];
                const int row = hc * 32 + nt * 8 + (lane & 7);
                const int col = kt * 16 + (lane & 8);
                ldsm_x2(bfr, sbase + SM_W0 + row * PITCH_W0 + col * 2);
                mma16816(c1[nt][0], afr[kt][0], bfr);
                mma16816(c1[nt][1], afr[kt][1], bfr);
            }
        }

        // relu + pack -> layer-2 A fragments; accumulate D2
        #pragma unroll
        for (int j = 0; j < 2; j++) {       // pair of n8 tiles = one k16 tile of layer2
            #pragma unroll
            for (int mt = 0; mt < 2; mt++) {
                uint32_t a2[4];
                a2[0] = pack2(fmaxf(c1[2 * j][mt][0], 0.0f),     fmaxf(c1[2 * j][mt][1], 0.0f));
                a2[1] = pack2(fmaxf(c1[2 * j][mt][2], 0.0f),     fmaxf(c1[2 * j][mt][3], 0.0f));
                a2[2] = pack2(fmaxf(c1[2 * j + 1][mt][0], 0.0f), fmaxf(c1[2 * j + 1][mt][1], 0.0f));
                a2[3] = pack2(fmaxf(c1[2 * j + 1][mt][2], 0.0f), fmaxf(c1[2 * j + 1][mt][3], 0.0f));
                mma16816(c2[mt][0], a2, w1fr[hc * 2 + j][0]);
                mma16816(c2[mt][1], a2, w1fr[hc * 2 + j][1]);
            }
        }
    }

    // ---------------- Stage update to SMEM ----------------
    {
        const int rowbase = warp * 32;
        #pragma unroll
        for (int mt = 0; mt < 2; mt++)
            #pragma unroll
            for (int n2 = 0; n2 < 2; n2++) {
                const int r0 = rowbase + mt * 16 + g;
                const int col = n2 * 8 + t * 2;
                s_upd[r0 * UPD_PITCH + col]           = c2[mt][n2][0];
                s_upd[r0 * UPD_PITCH + col + 1]       = c2[mt][n2][1];
                s_upd[(r0 + 8) * UPD_PITCH + col]     = c2[mt][n2][2];
                s_upd[(r0 + 8) * UPD_PITCH + col + 1] = c2[mt][n2][3];
            }
    }
    __syncthreads();

    // ---------------- Epilogue: out = x + update * mask (coalesced) ----------------
    {
        const float u = ru[((size_t)bb * HN + hh) * WN + wpix + tid];
        const float m = (u > 0.5f) ? 1.0f : 0.0f;
        #pragma unroll
        for (int c = 0; c < CN; c++) {
            const float xc  = s_halo[(c * 3 + 1) * HALO_PITCH + tid + 1];
            const float upd = s_upd[tid * UPD_PITCH + c];
            out[(((size_t)bb * CN + c) * HN + hh) * WN + wpix + tid] = xc + upd * m;
        }
    }
}

// ============================================================
// Launch
// ============================================================
extern "C" void kernel_launch(void* const* d_in, const int* in_sizes, int n_in,
                              void* d_out, int out_size) {
    (void)in_sizes; (void)n_in; (void)out_size;
    const float* x  = (const float*)d_in[0];
    const float* w0 = (const float*)d_in[1];
    const float* b0 = (const float*)d_in[2];
    const float* w1 = (const float*)d_in[3];
    const float* ru = (const float*)d_in[4];
    float* out = (float*)d_out;

    cudaFuncSetAttribute(ca_mlp_kernel,
                         cudaFuncAttributeMaxDynamicSharedMemorySize, SM_TOTAL);

    const int grid = BN * HN * (WN / TILE);   // 8192
    ca_mlp_kernel<<<grid, 128, SM_TOTAL>>>(x, w0, b0, w1, ru, out);
}

// round 3
// speedup vs baseline: 1.9953x; 1.9953x over previous
#include <cuda_runtime.h>
#include <cuda_fp16.h>
#include <cstdint>

// ============================================================
// Problem constants
// ============================================================
#define BN   4
#define CN   16
#define HN   512
#define WN   512
#define HID  128
#define TILE 128      // pixels per row-tile; CTA does 2 rows x 128 px

#define HALO_PITCH 132

// SMEM byte offsets (16B aligned). Total 110848 B -> 2 CTAs/SM.
#define SM_HALO  0                       // 16ch * 4 rows * 132 * f32 = 33792
#define SM_A     33792                   // A: 256 rows * 144 B (f16 x 64, pitch-padded)
#define PITCH_A  144
#define SM_W0    70656                   // w0: 128 rows * 144 B = 18432
#define PITCH_W0 144
#define SM_W1    89088                   // w1: 16 rows * 272 B = 4352
#define PITCH_W1 272
#define SM_UPD   93440                   // update stage: 256 * 17 * f32 = 17408
#define UPD_PITCH 17
#define SM_TOTAL 110848

// ============================================================
// PTX helpers (base sm_103-compatible: ldmatrix + mma.sync)
// ============================================================
__device__ __forceinline__ uint32_t smem_u32(const void* p) {
    uint32_t a;
    asm("{ .reg .u64 t; cvta.to.shared.u64 t, %1; cvt.u32.u64 %0, t; }"
        : "=r"(a) : "l"(p));
    return a;
}

__device__ __forceinline__ void ldsm_x4(uint32_t* r, uint32_t addr) {
    asm volatile("ldmatrix.sync.aligned.m8n8.x4.shared.b16 {%0,%1,%2,%3}, [%4];"
                 : "=r"(r[0]), "=r"(r[1]), "=r"(r[2]), "=r"(r[3]) : "r"(addr));
}
__device__ __forceinline__ void ldsm_x2(uint32_t* r, uint32_t addr) {
    asm volatile("ldmatrix.sync.aligned.m8n8.x2.shared.b16 {%0,%1}, [%2];"
                 : "=r"(r[0]), "=r"(r[1]) : "r"(addr));
}

// D += A * B  (m16n8k16, f16 in, f32 accum)
__device__ __forceinline__ void mma16816(float* c, const uint32_t* a, const uint32_t* b) {
    asm volatile("mma.sync.aligned.m16n8k16.row.col.f32.f16.f16.f32 "
                 "{%0,%1,%2,%3}, {%4,%5,%6,%7}, {%8,%9}, {%0,%1,%2,%3};"
                 : "+f"(c[0]), "+f"(c[1]), "+f"(c[2]), "+f"(c[3])
                 : "r"(a[0]), "r"(a[1]), "r"(a[2]), "r"(a[3]),
                   "r"(b[0]), "r"(b[1]));
}

__device__ __forceinline__ uint32_t pack2(float a, float b) {
    __half2 h = __floats2half2_rn(a, b);
    return *reinterpret_cast<uint32_t*>(&h);
}

// ============================================================
// Kernel: one CTA = 2 adjacent image rows x 128 pixels (256 "M rows").
// 8 warps; warp w owns M-rows [32w, 32w+32).
// Layer1: D1[32x128] = A[32x64] * W0^T  (bias folded at k=48)
// Layer2: D2[32x16]  = relu(D1) * W1^T, fused in registers (layer1
//   C-fragment == layer2 A-fragment; adjacent n8 tiles = k16 halves).
// ============================================================
__global__ void __launch_bounds__(256, 2) ca_mlp_kernel(
    const float* __restrict__ x,
    const float* __restrict__ w0,
    const float* __restrict__ b0,
    const float* __restrict__ w1,
    const float* __restrict__ ru,
    float* __restrict__ out)
{
    extern __shared__ char smem[];
    const uint32_t sbase = smem_u32(smem);
    float* s_halo = reinterpret_cast<float*>(smem + SM_HALO);
    float* s_upd  = reinterpret_cast<float*>(smem + SM_UPD);

    const int tid  = threadIdx.x;
    const int warp = tid >> 5;
    const int lane = tid & 31;
    const int g    = lane >> 2;
    const int t    = lane & 3;

    const int bx   = blockIdx.x;
    const int wt   = bx & 3;                 // column tile
    const int hblk = (bx >> 2) & 255;        // row pair
    const int bb   = bx >> 10;               // batch
    const int h0   = hblk * 2;
    const int wpix = wt * TILE;

    // ---------------- Load weights to SMEM ----------------
    // w0: [128][64] f16; k<48 = w0, k==48 = b0 (bias-as-K), else 0
    for (int idx = tid; idx < 128 * 32; idx += 256) {
        const int o = idx >> 5;
        const int kp = (idx & 31) * 2;
        float v0 = 0.0f, v1 = 0.0f;
        if (kp < 48)      { v0 = w0[o * 48 + kp]; v1 = (kp + 1 < 48) ? w0[o * 48 + kp + 1] : 0.0f; }
        else if (kp == 48) v0 = b0[o];
        *reinterpret_cast<uint32_t*>(smem + SM_W0 + o * PITCH_W0 + kp * 2) = pack2(v0, v1);
    }
    // w1: [16][128] f16
    for (int idx = tid; idx < 16 * 64; idx += 256) {
        const int o = idx >> 6;
        const int kp = (idx & 63) * 2;
        *reinterpret_cast<uint32_t*>(smem + SM_W1 + o * PITCH_W1 + kp * 2) =
            pack2(w1[o * 128 + kp], w1[o * 128 + kp + 1]);
    }
    // x halo: 16 ch x 4 rows (h0-1 .. h0+2) x 130 cols, zero-padded
    for (int idx = tid; idx < CN * 4 * 130; idx += 256) {
        const int c = idx / 520;
        const int rem = idx - c * 520;
        const int r = rem / 130;
        const int j = rem - r * 130;
        const int gh = h0 + r - 1;
        const int gw = wpix + j - 1;
        float v = 0.0f;
        if ((unsigned)gh < (unsigned)HN && (unsigned)gw < (unsigned)WN)
            v = x[(((size_t)bb * CN + c) * HN + gh) * WN + gw];
        s_halo[(c * 4 + r) * HALO_PITCH + j] = v;
    }
    __syncthreads();

    // ---------------- Sobel features -> SMEM A (thread tid = M-row tid) ----------------
    {
        const int r = tid >> 7;          // row within pair (0/1)
        const int p = tid & 127;         // pixel within tile
        uint32_t* arow = reinterpret_cast<uint32_t*>(smem + SM_A + tid * PITCH_A);
        #pragma unroll
        for (int cp = 0; cp < 8; cp++) {
            float xv[2], gx[2], gy[2];
            #pragma unroll
            for (int e = 0; e < 2; e++) {
                const int c = cp * 2 + e;
                const float* hb = &s_halo[(c * 4 + r) * HALO_PITCH + p];
                const float p00 = hb[0], p01 = hb[1], p02 = hb[2];
                const float p10 = hb[HALO_PITCH],     p11 = hb[HALO_PITCH + 1],     p12 = hb[HALO_PITCH + 2];
                const float p20 = hb[2 * HALO_PITCH], p21 = hb[2 * HALO_PITCH + 1], p22 = hb[2 * HALO_PITCH + 2];
                xv[e] = p11;
                gx[e] = (p02 - p00) + 2.0f * (p12 - p10) + (p22 - p20);
                gy[e] = (p20 + 2.0f * p21 + p22) - (p00 + 2.0f * p01 + p02);
            }
            arow[cp]      = pack2(xv[0], xv[1]);
            arow[8 + cp]  = pack2(gx[0], gx[1]);
            arow[16 + cp] = pack2(gy[0], gy[1]);
        }
        arow[24] = pack2(1.0f, 0.0f);   // k=48 multiplies the b0 column
        #pragma unroll
        for (int i = 25; i < 32; i++) arow[i] = 0u;
    }
    __syncthreads();

    // ---------------- Fused MLP (per warp: 32 M-rows) ----------------
    const int m0 = warp * 32;
    float c2[2][2][4];
    #pragma unroll
    for (int mt = 0; mt < 2; mt++)
        #pragma unroll
        for (int n2 = 0; n2 < 2; n2++)
            #pragma unroll
            for (int j = 0; j < 4; j++) c2[mt][n2][j] = 0.0f;

    #pragma unroll
    for (int hc = 0; hc < 4; hc++) {        // hidden chunk of 32 units
        float c1[4][2][4];
        #pragma unroll
        for (int nt = 0; nt < 4; nt++)
            #pragma unroll
            for (int mt = 0; mt < 2; mt++)
                #pragma unroll
                for (int j = 0; j < 4; j++) c1[nt][mt][j] = 0.0f;

        #pragma unroll
        for (int kt = 0; kt < 4; kt++) {
            uint32_t afr0[4], afr1[4];
            {
                const int col = kt * 16 + ((lane >> 4) << 3);
                ldsm_x4(afr0, sbase + SM_A + (m0 + (lane & 15)) * PITCH_A + col * 2);
                ldsm_x4(afr1, sbase + SM_A + (m0 + 16 + (lane & 15)) * PITCH_A + col * 2);
            }
            #pragma unroll
            for (int nt = 0; nt < 4; nt++) {
                uint32_t bfr[2];
                const int row = hc * 32 + nt * 8 + (lane & 7);
                const int col = kt * 16 + (lane & 8);
                ldsm_x2(bfr, sbase + SM_W0 + row * PITCH_W0 + col * 2);
                mma16816(c1[nt][0], afr0, bfr);
                mma16816(c1[nt][1], afr1, bfr);
            }
        }

        // relu + pack -> layer-2 A frags; accumulate D2
        #pragma unroll
        for (int j = 0; j < 2; j++) {       // n8-tile pair = one k16 tile
            uint32_t w1a[2], w1b[2];
            {
                const int col = (hc * 2 + j) * 16 + (lane & 8);
                ldsm_x2(w1a, sbase + SM_W1 + (lane & 7) * PITCH_W1 + col * 2);
                ldsm_x2(w1b, sbase + SM_W1 + (8 + (lane & 7)) * PITCH_W1 + col * 2);
            }
            #pragma unroll
            for (int mt = 0; mt < 2; mt++) {
                uint32_t a2[4];
                a2[0] = pack2(fmaxf(c1[2 * j][mt][0], 0.0f),     fmaxf(c1[2 * j][mt][1], 0.0f));
                a2[1] = pack2(fmaxf(c1[2 * j][mt][2], 0.0f),     fmaxf(c1[2 * j][mt][3], 0.0f));
                a2[2] = pack2(fmaxf(c1[2 * j + 1][mt][0], 0.0f), fmaxf(c1[2 * j + 1][mt][1], 0.0f));
                a2[3] = pack2(fmaxf(c1[2 * j + 1][mt][2], 0.0f), fmaxf(c1[2 * j + 1][mt][3], 0.0f));
                mma16816(c2[mt][0], a2, w1a);
                mma16816(c2[mt][1], a2, w1b);
            }
        }
    }

    // ---------------- Stage update to SMEM ----------------
    {
        #pragma unroll
        for (int mt = 0; mt < 2; mt++)
            #pragma unroll
            for (int n2 = 0; n2 < 2; n2++) {
                const int r0 = m0 + mt * 16 + g;
                const int col = n2 * 8 + t * 2;
                s_upd[r0 * UPD_PITCH + col]           = c2[mt][n2][0];
                s_upd[r0 * UPD_PITCH + col + 1]       = c2[mt][n2][1];
                s_upd[(r0 + 8) * UPD_PITCH + col]     = c2[mt][n2][2];
                s_upd[(r0 + 8) * UPD_PITCH + col + 1] = c2[mt][n2][3];
            }
    }
    __syncthreads();

    // ---------------- Epilogue: out = x + update * mask (coalesced) ----------------
    {
        const int r = tid >> 7;
        const int p = tid & 127;
        const int h = h0 + r;
        const float u = ru[((size_t)bb * HN + h) * WN + wpix + p];
        const float m = (u > 0.5f) ? 1.0f : 0.0f;
        #pragma unroll
        for (int c = 0; c < CN; c++) {
            const float xc  = s_halo[(c * 4 + r + 1) * HALO_PITCH + p + 1];
            const float upd = s_upd[tid * UPD_PITCH + c];
            out[(((size_t)bb * CN + c) * HN + h) * WN + wpix + p] = xc + upd * m;
        }
    }
}

// ============================================================
// Launch
// ============================================================
extern "C" void kernel_launch(void* const* d_in, const int* in_sizes, int n_in,
                              void* d_out, int out_size) {
    (void)in_sizes; (void)n_in; (void)out_size;
    const float* x  = (const float*)d_in[0];
    const float* w0 = (const float*)d_in[1];
    const float* b0 = (const float*)d_in[2];
    const float* w1 = (const float*)d_in[3];
    const float* ru = (const float*)d_in[4];
    float* out = (float*)d_out;

    cudaFuncSetAttribute(ca_mlp_kernel,
                         cudaFuncAttributeMaxDynamicSharedMemorySize, SM_TOTAL);

    const int grid = BN * (HN / 2) * (WN / TILE);   // 4096
    ca_mlp_kernel<<<grid, 256, SM_TOTAL>>>(x, w0, b0, w1, ru, out);
}

// round 6
// speedup vs baseline: 4.5739x; 2.2923x over previous
#include <cuda_runtime.h>
#include <cuda_fp16.h>
#include <cstdint>

// ============================================================
// Problem constants
// ============================================================
#define BN   4
#define CN   16
#define HN   512
#define WN   512
#define HID  128
#define TILE 128      // pixels per row-tile; CTA = 2 rows x 128 px = 256 M-rows

// SMEM (byte offsets). Total 47872 B -> 3 CTAs/SM.
#define SM_A     0          // A: 256 rows x 112 B (f16 x 48); later aliased as update stage
#define PITCH_A  112
#define SM_W0    28672      // w0: 128 rows x 112 B (f16 x 48)
#define PITCH_W0 112
#define SM_W1    43008      // w1: 16 rows x 272 B (f16 x 128)
#define PITCH_W1 272
#define SM_BIAS  47360      // b0: 128 f32
#define SM_TOTAL 47872

// ============================================================
// PTX helpers (base sm_103-compatible: ldmatrix + mma.sync)
// ============================================================
__device__ __forceinline__ uint32_t smem_u32(const void* p) {
    uint32_t a;
    asm("{ .reg .u64 t; cvta.to.shared.u64 t, %1; cvt.u32.u64 %0, t; }"
        : "=r"(a) : "l"(p));
    return a;
}

__device__ __forceinline__ void ldsm_x4(uint32_t* r, uint32_t addr) {
    asm volatile("ldmatrix.sync.aligned.m8n8.x4.shared.b16 {%0,%1,%2,%3}, [%4];"
                 : "=r"(r[0]), "=r"(r[1]), "=r"(r[2]), "=r"(r[3]) : "r"(addr));
}
__device__ __forceinline__ void ldsm_x2(uint32_t* r, uint32_t addr) {
    asm volatile("ldmatrix.sync.aligned.m8n8.x2.shared.b16 {%0,%1}, [%2];"
                 : "=r"(r[0]), "=r"(r[1]) : "r"(addr));
}

// D += A * B  (m16n8k16, f16 in, f32 accum)
__device__ __forceinline__ void mma16816(float* c, const uint32_t* a, const uint32_t* b) {
    asm volatile("mma.sync.aligned.m16n8k16.row.col.f32.f16.f16.f32 "
                 "{%0,%1,%2,%3}, {%4,%5,%6,%7}, {%8,%9}, {%0,%1,%2,%3};"
                 : "+f"(c[0]), "+f"(c[1]), "+f"(c[2]), "+f"(c[3])
                 : "r"(a[0]), "r"(a[1]), "r"(a[2]), "r"(a[3]),
                   "r"(b[0]), "r"(b[1]));
}

__device__ __forceinline__ uint32_t pack2(float a, float b) {
    __half2 h = __floats2half2_rn(a, b);
    return *reinterpret_cast<uint32_t*>(&h);
}

// ============================================================
// Kernel: one CTA = 2 adjacent image rows x 128 pixels.
// Phase 1 (Sobel): thread = (channel-half, column); separable Sobel from
//   global memory with shfl for horizontal neighbors; features -> SMEM A (f16).
// Phase 2 (MLP): 8 warps, warp w owns M-rows [32w,32w+32).
//   Layer1: c1[32x16] = A[32x48] * W0^T(16-chunk) + b0 (fp32 init)
//   Layer2: c2 += relu(c1) * W1^T, fused in registers.
// Phase 3: epilogue, x re-read from gmem (L2-hot).
// ============================================================
__global__ void __launch_bounds__(256, 3) ca_mlp_kernel(
    const float* __restrict__ x,
    const float* __restrict__ w0,
    const float* __restrict__ b0,
    const float* __restrict__ w1,
    const float* __restrict__ ru,
    float* __restrict__ out)
{
    extern __shared__ char smem[];
    const uint32_t sbase = smem_u32(smem);

    const int tid  = threadIdx.x;
    const int warp = tid >> 5;
    const int lane = tid & 31;

    const int bx   = blockIdx.x;
    const int wt   = bx & 3;                 // column tile
    const int hblk = (bx >> 2) & 255;        // row pair
    const int bb   = bx >> 10;               // batch
    const int h0   = hblk * 2;
    const int wpix = wt * TILE;

    // ---------------- Load weights / bias to SMEM ----------------
    // w0: [128][48] f16
    for (int idx = tid; idx < 128 * 24; idx += 256) {
        const int o = idx / 24;
        const int k = (idx - o * 24) * 2;
        *reinterpret_cast<uint32_t*>(smem + SM_W0 + o * PITCH_W0 + k * 2) =
            pack2(w0[o * 48 + k], w0[o * 48 + k + 1]);
    }
    // w1: [16][128] f16
    for (int idx = tid; idx < 16 * 64; idx += 256) {
        const int o = idx >> 6;
        const int k = (idx & 63) * 2;
        *reinterpret_cast<uint32_t*>(smem + SM_W1 + o * PITCH_W1 + k * 2) =
            pack2(w1[o * 128 + k], w1[o * 128 + k + 1]);
    }
    // bias f32
    if (tid < 128)
        *reinterpret_cast<float*>(smem + SM_BIAS + tid * 4) = b0[tid];

    // ---------------- Phase 1: Sobel from gmem -> SMEM A ----------------
    {
        const int g8   = tid >> 7;           // channel half (0: ch 0-7, 1: ch 8-15)
        const int pcol = tid & 127;          // column within tile
        const int P    = wpix + pcol;        // global column
        const int c0   = g8 * 8;

        // row validity (rows h0-1 .. h0+2)
        const bool r0ok = (h0 - 1) >= 0;
        const bool r3ok = (h0 + 2) < HN;

        const bool isL = (lane == 0);
        const bool isR = (lane == 31);
        const int  Pe  = isL ? (P - 1) : (P + 1);
        const bool peok = (isL || isR) && ((unsigned)Pe < (unsigned)WN);

        char* rowt = smem + SM_A + pcol * PITCH_A;          // M-row = pcol (row h0)
        char* rowb = smem + SM_A + (128 + pcol) * PITCH_A;  // M-row = 128+pcol (row h0+1)

        #pragma unroll
        for (int cp = 0; cp < 4; cp++) {
            float xvt[2], xvb[2], gxt[2], gxb[2], gyt[2], gyb[2];
            #pragma unroll
            for (int e = 0; e < 2; e++) {
                const int c = c0 + cp * 2 + e;
                const float* base = x + (((size_t)bb * CN + c) * HN) * WN;
                const float* col  = base + (size_t)(h0 - 1) * WN + P;
                const float x0 = r0ok ? col[0]          : 0.0f;
                const float x1 =        col[WN];
                const float x2 =        col[2 * WN];
                const float x3 = r3ok ? col[3 * WN]     : 0.0f;

                const float s0 = x0 + 2.0f * x1 + x2;
                const float s1 = x1 + 2.0f * x2 + x3;
                const float d0 = x2 - x0;
                const float d1 = x3 - x1;

                // edge column (lane 0 -> P-1, lane 31 -> P+1), zero-padded
                float se0 = 0.0f, se1 = 0.0f, de0 = 0.0f, de1 = 0.0f;
                if (peok) {
                    const float* ecol = base + (size_t)(h0 - 1) * WN + Pe;
                    const float e0 = r0ok ? ecol[0]      : 0.0f;
                    const float e1 =        ecol[WN];
                    const float e2 =        ecol[2 * WN];
                    const float e3 = r3ok ? ecol[3 * WN] : 0.0f;
                    se0 = e0 + 2.0f * e1 + e2;
                    se1 = e1 + 2.0f * e2 + e3;
                    de0 = e2 - e0;
                    de1 = e3 - e1;
                }

                float sl0 = __shfl_up_sync(0xffffffffu, s0, 1);
                float sl1 = __shfl_up_sync(0xffffffffu, s1, 1);
                float dl0 = __shfl_up_sync(0xffffffffu, d0, 1);
                float dl1 = __shfl_up_sync(0xffffffffu, d1, 1);
                float sr0 = __shfl_down_sync(0xffffffffu, s0, 1);
                float sr1 = __shfl_down_sync(0xffffffffu, s1, 1);
                float dr0 = __shfl_down_sync(0xffffffffu, d0, 1);
                float dr1 = __shfl_down_sync(0xffffffffu, d1, 1);
                if (isL) { sl0 = se0; sl1 = se1; dl0 = de0; dl1 = de1; }
                if (isR) { sr0 = se0; sr1 = se1; dr0 = de0; dr1 = de1; }

                xvt[e] = x1;
                xvb[e] = x2;
                gxt[e] = sr0 - sl0;
                gxb[e] = sr1 - sl1;
                gyt[e] = dl0 + 2.0f * d0 + dr0;
                gyb[e] = dl1 + 2.0f * d1 + dr1;
            }
            // feature cols (halves): xv at c, gx at 16+c, gy at 32+c
            const int c = c0 + cp * 2;
            *reinterpret_cast<uint32_t*>(rowt + c * 2)        = pack2(xvt[0], xvt[1]);
            *reinterpret_cast<uint32_t*>(rowt + (16 + c) * 2) = pack2(gxt[0], gxt[1]);
            *reinterpret_cast<uint32_t*>(rowt + (32 + c) * 2) = pack2(gyt[0], gyt[1]);
            *reinterpret_cast<uint32_t*>(rowb + c * 2)        = pack2(xvb[0], xvb[1]);
            *reinterpret_cast<uint32_t*>(rowb + (16 + c) * 2) = pack2(gxb[0], gxb[1]);
            *reinterpret_cast<uint32_t*>(rowb + (32 + c) * 2) = pack2(gyb[0], gyb[1]);
        }
    }
    __syncthreads();

    // ---------------- Phase 2: fused MLP (per warp: 32 M-rows) ----------------
    const int m0 = warp * 32;
    const int t  = lane & 3;
    const int g  = lane >> 2;

    float c2[2][2][4];
    #pragma unroll
    for (int mt = 0; mt < 2; mt++)
        #pragma unroll
        for (int n2 = 0; n2 < 2; n2++)
            #pragma unroll
            for (int j = 0; j < 4; j++) c2[mt][n2][j] = 0.0f;

    #pragma unroll
    for (int hcj = 0; hcj < 8; hcj++) {       // 16 hidden units per chunk
        // bias init (fp32 exact): cols hcj*16 + nt*8 + t*2 + {0,1}
        float c1[2][2][4];
        #pragma unroll
        for (int nt = 0; nt < 2; nt++) {
            const float2 b = *reinterpret_cast<const float2*>(
                smem + SM_BIAS + (hcj * 16 + nt * 8 + t * 2) * 4);
            #pragma unroll
            for (int mt = 0; mt < 2; mt++) {
                c1[nt][mt][0] = b.x; c1[nt][mt][1] = b.y;
                c1[nt][mt][2] = b.x; c1[nt][mt][3] = b.y;
            }
        }

        #pragma unroll
        for (int kt = 0; kt < 3; kt++) {
            uint32_t afr0[4], afr1[4];
            const uint32_t acol = kt * 32 + ((lane >> 4) << 4);
            ldsm_x4(afr0, sbase + SM_A + (m0 + (lane & 15)) * PITCH_A + acol);
            ldsm_x4(afr1, sbase + SM_A + (m0 + 16 + (lane & 15)) * PITCH_A + acol);
            #pragma unroll
            for (int nt = 0; nt < 2; nt++) {
                uint32_t bfr[2];
                const int row = hcj * 16 + nt * 8 + (lane & 7);
                ldsm_x2(bfr, sbase + SM_W0 + row * PITCH_W0 + kt * 32 + (lane & 8) * 2);
                mma16816(c1[nt][0], afr0, bfr);
                mma16816(c1[nt][1], afr1, bfr);
            }
        }

        // layer 2: relu+pack -> k16 A-frag; accumulate
        uint32_t w1a[2], w1b[2];
        {
            const uint32_t wcol = hcj * 32 + (lane & 8) * 2;
            ldsm_x2(w1a, sbase + SM_W1 + (lane & 7) * PITCH_W1 + wcol);
            ldsm_x2(w1b, sbase + SM_W1 + (8 + (lane & 7)) * PITCH_W1 + wcol);
        }
        #pragma unroll
        for (int mt = 0; mt < 2; mt++) {
            uint32_t a2[4];
            a2[0] = pack2(fmaxf(c1[0][mt][0], 0.0f), fmaxf(c1[0][mt][1], 0.0f));
            a2[1] = pack2(fmaxf(c1[0][mt][2], 0.0f), fmaxf(c1[0][mt][3], 0.0f));
            a2[2] = pack2(fmaxf(c1[1][mt][0], 0.0f), fmaxf(c1[1][mt][1], 0.0f));
            a2[3] = pack2(fmaxf(c1[1][mt][2], 0.0f), fmaxf(c1[1][mt][3], 0.0f));
            mma16816(c2[mt][0], a2, w1a);
            mma16816(c2[mt][1], a2, w1b);
        }
    }

    // ---------------- Stage update into A region (per-warp rows, safe alias) ----------------
    {
        #pragma unroll
        for (int mt = 0; mt < 2; mt++)
            #pragma unroll
            for (int n2 = 0; n2 < 2; n2++) {
                const int r0 = m0 + mt * 16 + g;
                const int col = n2 * 8 + t * 2;
                float* p0 = reinterpret_cast<float*>(smem + SM_A + r0 * PITCH_A);
                float* p1 = reinterpret_cast<float*>(smem + SM_A + (r0 + 8) * PITCH_A);
                p0[col]     = c2[mt][n2][0];
                p0[col + 1] = c2[mt][n2][1];
                p1[col]     = c2[mt][n2][2];
                p1[col + 1] = c2[mt][n2][3];
            }
    }
    __syncthreads();

    // ---------------- Phase 3: epilogue out = x + update * mask ----------------
    {
        const int r = tid >> 7;
        const int p = tid & 127;
        const int h = h0 + r;
        const float u = ru[((size_t)bb * HN + h) * WN + wpix + p];
        const float m = (u > 0.5f) ? 1.0f : 0.0f;
        const float* updrow = reinterpret_cast<const float*>(smem + SM_A + tid * PITCH_A);
        #pragma unroll
        for (int c = 0; c < CN; c++) {
            const size_t gi = (((size_t)bb * CN + c) * HN + h) * WN + wpix + p;
            out[gi] = x[gi] + updrow[c] * m;
        }
    }
}

// ============================================================
// Launch
// ============================================================
extern "C" void kernel_launch(void* const* d_in, const int* in_sizes, int n_in,
                              void* d_out, int out_size) {
    (void)in_sizes; (void)n_in; (void)out_size;
    const float* x  = (const float*)d_in[0];
    const float* w0 = (const float*)d_in[1];
    const float* b0 = (const float*)d_in[2];
    const float* w1 = (const float*)d_in[3];
    const float* ru = (const float*)d_in[4];
    float* out = (float*)d_out;

    const int grid = BN * (HN / 2) * (WN / TILE);   // 4096
    ca_mlp_kernel<<<grid, 256, SM_TOTAL>>>(x, w0, b0, w1, ru, out);
}